// round 15
// baseline (speedup 1.0000x reference)
#include <cuda_runtime.h>
#include <cuda_fp16.h>
#include <math.h>
#include <stdint.h>

#define N_NODES 768
#define WAV 6360
#define HID 32
#define NH 4
#define GC 128          // H*HID
#define GC2 256         // [g_l | g_r]
#define P_PATCH 8
#define SUP 96

#define GSPLITS 24
#define CHUNK 288       // 24*288 = 6912 >= 6360 (tail zero-filled)
#define NSTAGE 9        // CHUNK / 32
#define MTILE 128
#define NMB (N_NODES / MTILE)   // 6

#define ASTR 40                 // A smem row stride (halfs)
#define A_HALF (MTILE * ASTR)   // 5120 halfs = 10240 B per half-matrix stage
#define BSTR 264                // B smem row stride (halfs) -> 528 B rows
#define B_IMG 16896             // 32 rows * 528 B (one half-matrix)
#define B_BLK 33792             // hi + lo

// device scratch (no allocation allowed)
__device__ float  d_Gp[GSPLITS * N_NODES * GC2];
__device__ float  d_G1[N_NODES * GC2];
__device__ float  d_G2[N_NODES * GC2];
__device__ float  d_z1[N_NODES * HID];
__device__ float  d_es[NH * N_NODES * N_NODES];   // e scores [h][i][j]
__device__ __half d_Wimg[GSPLITS * NSTAGE * B_BLK / 2];   // padded B stage images
__device__ int    d_cnt[NMB];                     // split-completion counters

// ---------------------------------------------------------------------------
__device__ __forceinline__ uint32_t smem_u32(const void* p) {
    uint32_t a;
    asm("{ .reg .u64 t; cvta.to.shared.u64 t, %1; cvt.u32.u64 %0, t; }"
        : "=r"(a) : "l"(p));
    return a;
}
__device__ __forceinline__ void ldsm_x4(uint32_t* r, uint32_t a) {
    asm volatile("ldmatrix.sync.aligned.m8n8.x4.shared.b16 {%0,%1,%2,%3}, [%4];"
                 : "=r"(r[0]), "=r"(r[1]), "=r"(r[2]), "=r"(r[3]) : "r"(a));
}
__device__ __forceinline__ void ldsm_x4t(uint32_t* r, uint32_t a) {
    asm volatile("ldmatrix.sync.aligned.m8n8.x4.trans.shared.b16 {%0,%1,%2,%3}, [%4];"
                 : "=r"(r[0]), "=r"(r[1]), "=r"(r[2]), "=r"(r[3]) : "r"(a));
}
__device__ __forceinline__ void mma_f16(float* c, const uint32_t* a, const uint32_t* b) {
    asm volatile("mma.sync.aligned.m16n8k16.row.col.f32.f16.f16.f32 "
                 "{%0,%1,%2,%3}, {%4,%5,%6,%7}, {%8,%9}, {%0,%1,%2,%3};"
                 : "+f"(c[0]), "+f"(c[1]), "+f"(c[2]), "+f"(c[3])
                 : "r"(a[0]), "r"(a[1]), "r"(a[2]), "r"(a[3]), "r"(b[0]), "r"(b[1]));
}
__device__ __forceinline__ void bulk_cp(uint32_t dst, const void* src, uint32_t bytes,
                                        uint32_t mbar) {
    asm volatile(
        "cp.async.bulk.shared::cluster.global.mbarrier::complete_tx::bytes "
        "[%0], [%1], %2, [%3];"
        :: "r"(dst), "l"(src), "r"(bytes), "r"(mbar) : "memory");
}
#define MBAR_INIT(a, n) \
    asm volatile("mbarrier.init.shared.b64 [%0], %1;" :: "r"(a), "r"(n) : "memory")
#define MBAR_INVAL(a) \
    asm volatile("mbarrier.inval.shared.b64 [%0];" :: "r"(a) : "memory")
#define MBAR_EXPECT(a, b) \
    asm volatile("mbarrier.arrive.expect_tx.shared.b64 _, [%0], %1;" \
                 :: "r"(a), "r"((uint32_t)(b)) : "memory")

__device__ __forceinline__ void mbar_wait(uint32_t mbar, uint32_t parity) {
    uint32_t done;
    asm volatile("{\n\t.reg .pred p;\n\t"
                 "mbarrier.try_wait.parity.acquire.cta.shared::cta.b64 p, [%1], %2;\n\t"
                 "selp.b32 %0, 1, 0, p;\n\t}"
                 : "=r"(done) : "r"(mbar), "r"(parity) : "memory");
    if (!done) {
        asm volatile("{\n\t.reg .pred P1;\n\t"
                     "W1_%=:\n\t"
                     "mbarrier.try_wait.parity.acquire.cta.shared::cta.b64 P1, [%0], %1, 0x989680;\n\t"
                     "@P1 bra.uni W2_%=;\n\t"
                     "bra.uni W1_%=;\n\t"
                     "W2_%=:\n\t}"
                     :: "r"(mbar), "r"(parity) : "memory");
    }
}

// ---------------------------------------------------------------------------
// split_w: [Wl|Wr] fp32 -> per-(s,st) padded smem images (hi | lo)
__global__ void split_w(const float* __restrict__ Wl, const float* __restrict__ Wr,
                        __half* __restrict__ Wi) {
    int blk = blockIdx.x;                 // s*NSTAGE + st
    int st = blk % NSTAGE, s = blk / NSTAGE;
    int tid = threadIdx.x;                // 256
    int k = tid >> 3, n0 = (tid & 7) * 32;
    int kg = s * CHUNK + st * 32 + k;

    __half hi[32], lo[32];
    if (kg < WAV) {
#pragma unroll
        for (int q = 0; q < 32; q += 2) {
            int n = n0 + q;
            float v0 = (n < GC) ? Wl[(size_t)kg * GC + n]
                                : Wr[(size_t)kg * GC + (n - GC)];
            float v1 = (n + 1 < GC) ? Wl[(size_t)kg * GC + n + 1]
                                    : Wr[(size_t)kg * GC + (n + 1 - GC)];
            __half2 h2 = __floats2half2_rn(v0, v1);
            float2 bk = __half22float2(h2);
            __half2 l2 = __floats2half2_rn(v0 - bk.x, v1 - bk.y);
            *(__half2*)(hi + q) = h2;
            *(__half2*)(lo + q) = l2;
        }
    } else {
#pragma unroll
        for (int q = 0; q < 32; q++) { hi[q] = __float2half_rn(0.f); lo[q] = hi[q]; }
    }
    char* dst = (char*)Wi + (size_t)blk * B_BLK + k * 528 + n0 * 2;
#pragma unroll
    for (int q = 0; q < 4; q++) {
        *(uint4*)(dst + q * 16)         = *(uint4*)(hi + q * 8);
        *(uint4*)(dst + B_IMG + q * 16) = *(uint4*)(lo + q * 8);
    }
}

// ---------------------------------------------------------------------------
// fp16-split tensor-core GEMM + fused last-block split reduction.
__global__ void __launch_bounds__(512, 1)
gemm_tc(const float* __restrict__ X,
        const __half* __restrict__ Wi,
        float* __restrict__ Gp,
        float* __restrict__ G,
        int* __restrict__ cnt) {
    extern __shared__ __half sm[];
    __half* Ah = sm;                      // [2][A_HALF]
    __half* Al = Ah + 2 * A_HALF;         // [2][A_HALF]
    char*   Bb = (char*)(sm + 4 * A_HALF);    // [2][B_BLK]
    uint32_t sAh = smem_u32(Ah);
    uint32_t sAl = smem_u32(Al);
    uint32_t sB  = smem_u32(Bb);
    uint32_t mbar = sB + 2 * B_BLK;

    __shared__ int isLast;

    int bm = blockIdx.x, s = blockIdx.y;
    int tid = threadIdx.x, lane = tid & 31, w = tid >> 5;
    int wm = w >> 2, wn = w & 3;
    int m0 = bm * MTILE;
    int k0 = s * CHUNK;

    if (tid == 0) { MBAR_INIT(mbar, 1); MBAR_INIT(mbar + 8, 1); }
    __syncthreads();

    const char* Bbase = (const char*)Wi + (size_t)(s * NSTAGE) * B_BLK;
    int arow = tid >> 2, aq = (tid & 3) * 4;

    auto issueB = [&](int st) {
        if (tid == 0) {
            uint32_t mb = mbar + (st & 1) * 8;
            MBAR_EXPECT(mb, B_BLK);
            bulk_cp(sB + (st & 1) * B_BLK, Bbase + (size_t)st * B_BLK, B_BLK, mb);
        }
    };

    float acc[2][8][4];
#pragma unroll
    for (int mt = 0; mt < 2; mt++)
#pragma unroll
        for (int nt = 0; nt < 8; nt++)
#pragma unroll
            for (int c = 0; c < 4; c++) acc[mt][nt][c] = 0.f;

    float4 a0, a1;

    auto ldgA = [&](int st) {
        int kt = k0 + st * 32;
        const float* p = X + (size_t)(m0 + arow) * WAV + kt;
        a0 = (kt + aq + 3 < WAV) ? *(const float4*)(p + aq)
                                 : make_float4(
            (kt + aq + 0 < WAV) ? p[aq + 0] : 0.f,
            (kt + aq + 1 < WAV) ? p[aq + 1] : 0.f,
            (kt + aq + 2 < WAV) ? p[aq + 2] : 0.f,
            (kt + aq + 3 < WAV) ? p[aq + 3] : 0.f);
        a1 = (kt + aq + 19 < WAV) ? *(const float4*)(p + aq + 16)
                                  : make_float4(
            (kt + aq + 16 < WAV) ? p[aq + 16] : 0.f,
            (kt + aq + 17 < WAV) ? p[aq + 17] : 0.f,
            (kt + aq + 18 < WAV) ? p[aq + 18] : 0.f,
            (kt + aq + 19 < WAV) ? p[aq + 19] : 0.f);
    };
    auto stsA = [&](int st) {
        int base = (st & 1) * A_HALF + arow * ASTR;
#pragma unroll
        for (int hv = 0; hv < 2; hv++) {
            float4 v = hv ? a1 : a0;
            int off = base + aq + hv * 16;
            __half2 h0 = __floats2half2_rn(v.x, v.y);
            __half2 h1 = __floats2half2_rn(v.z, v.w);
            float2 b0 = __half22float2(h0);
            float2 b1 = __half22float2(h1);
            __half2 l0 = __floats2half2_rn(v.x - b0.x, v.y - b0.y);
            __half2 l1 = __floats2half2_rn(v.z - b1.x, v.w - b1.y);
            uint2 uh, ul;
            uh.x = *(uint32_t*)&h0; uh.y = *(uint32_t*)&h1;
            ul.x = *(uint32_t*)&l0; ul.y = *(uint32_t*)&l1;
            *(uint2*)(Ah + off) = uh;
            *(uint2*)(Al + off) = ul;
        }
    };
    auto compute = [&](int b) {
        uint32_t aOffH = sAh + (uint32_t)(b * A_HALF) * 2;
        uint32_t aOffL = sAl + (uint32_t)(b * A_HALF) * 2;
        uint32_t bOffH = sB + (uint32_t)(b * B_BLK);
        uint32_t bOffL = bOffH + B_IMG;
        int l15 = lane & 15, lhi = (lane >> 4) << 3;
#pragma unroll
        for (int k16 = 0; k16 < 32; k16 += 16) {
            uint32_t ah[2][4], al[2][4];
#pragma unroll
            for (int mt = 0; mt < 2; mt++) {
                uint32_t off = (uint32_t)((wm * 32 + mt * 16 + l15) * ASTR + k16 + lhi) * 2;
                ldsm_x4(ah[mt], aOffH + off);
                ldsm_x4(al[mt], aOffL + off);
            }
#pragma unroll
            for (int p = 0; p < 4; p++) {
                uint32_t offb = (uint32_t)((k16 + l15) * BSTR + wn * 64 + p * 16 + lhi) * 2;
                uint32_t bh[4], bl[4];
                ldsm_x4t(bh, bOffH + offb);
                ldsm_x4t(bl, bOffL + offb);
#pragma unroll
                for (int mt = 0; mt < 2; mt++) {
                    mma_f16(acc[mt][2 * p],     ah[mt], bh);
                    mma_f16(acc[mt][2 * p],     ah[mt], bl);
                    mma_f16(acc[mt][2 * p],     al[mt], bh);
                    mma_f16(acc[mt][2 * p + 1], ah[mt], bh + 2);
                    mma_f16(acc[mt][2 * p + 1], ah[mt], bl + 2);
                    mma_f16(acc[mt][2 * p + 1], al[mt], bh + 2);
                }
            }
        }
    };

    // prologue
    ldgA(0); stsA(0);
    issueB(0); issueB(1);
    for (int it = 0; it < NSTAGE; it++) {
        if (it + 1 < NSTAGE) ldgA(it + 1);
        mbar_wait(mbar + (it & 1) * 8, (it >> 1) & 1);
        __syncthreads();
        compute(it & 1);
        __syncthreads();
        if (it + 1 < NSTAGE) stsA(it + 1);
        if (it + 2 < NSTAGE) issueB(it + 2);
    }

    float* out = Gp + (size_t)s * N_NODES * GC2;
    int gid = lane >> 2, tig = lane & 3;
#pragma unroll
    for (int mt = 0; mt < 2; mt++) {
        int r = m0 + wm * 32 + mt * 16 + gid;
#pragma unroll
        for (int nt = 0; nt < 8; nt++) {
            int c = wn * 64 + nt * 8 + tig * 2;
            *(float2*)&out[(size_t)r * GC2 + c] =
                make_float2(acc[mt][nt][0], acc[mt][nt][1]);
            *(float2*)&out[(size_t)(r + 8) * GC2 + c] =
                make_float2(acc[mt][nt][2], acc[mt][nt][3]);
        }
    }
    __syncthreads();
    if (tid == 0) { MBAR_INVAL(mbar); MBAR_INVAL(mbar + 8); }

    // fused split reduction: last block of this m-stripe sums the 24 partials
    __threadfence();
    if (tid == 0) {
        int old = atomicAdd(&cnt[bm], 1);
        isLast = (old == GSPLITS - 1);
    }
    __syncthreads();
    if (isLast) {
        __threadfence();
        for (int i4 = tid; i4 < MTILE * GC2 / 4; i4 += 512) {
            int row = i4 >> 6, c4 = (i4 & 63) * 4;
            size_t off = (size_t)(m0 + row) * GC2 + c4;
            float4 sacc = make_float4(0.f, 0.f, 0.f, 0.f);
#pragma unroll
            for (int p = 0; p < GSPLITS; p++) {
                float4 v = *(const float4*)(Gp + (size_t)p * (N_NODES * GC2) + off);
                sacc.x += v.x; sacc.y += v.y; sacc.z += v.z; sacc.w += v.w;
            }
            *(float4*)(G + off) = sacc;
        }
        __syncthreads();
        if (tid == 0) cnt[bm] = 0;   // reset for next graph replay
    }
}

// ---------------------------------------------------------------------------
// e[i,j,h] = 1.5*(pr[i,h]+pl[j,h]) + sum_f (0.4 a_f)*|gr+gl|; h = blockIdx.z
// EXACT R11/R14 form (measured best)
__global__ void e_kernel(const float* __restrict__ G,
                         const int* __restrict__ adj,
                         const float* __restrict__ avec,
                         float* __restrict__ es) {
    __shared__ float grs[32][33];
    __shared__ float gls[64][33];
    __shared__ float asm_[32];
    __shared__ float prs[32];
    __shared__ float pls[64];

    int i0 = blockIdx.x * 32, j0 = blockIdx.y * 64, h = blockIdx.z;
    int tid = threadIdx.x;
    int tj = tid & 15, ti = tid >> 4;

    if (tid < 32) asm_[tid] = 0.4f * avec[tid];

    int adjv[2][4];
#pragma unroll
    for (int r = 0; r < 2; r++)
#pragma unroll
        for (int q = 0; q < 4; q++)
            adjv[r][q] = adj[(size_t)(i0 + ti * 2 + r) * N_NODES + j0 + tj + 16 * q];

    {
        int r = tid >> 3, fq = (tid & 7) * 4;
        float4 v = *(const float4*)(G + (size_t)(i0 + r) * GC2 + GC + h * 32 + fq);
        grs[r][fq + 0] = v.x; grs[r][fq + 1] = v.y;
        grs[r][fq + 2] = v.z; grs[r][fq + 3] = v.w;
    }
#pragma unroll
    for (int e2 = 0; e2 < 2; e2++) {
        int slot = tid + e2 * 256;
        int r = slot >> 3, fq = (slot & 7) * 4;
        float4 v = *(const float4*)(G + (size_t)(j0 + r) * GC2 + h * 32 + fq);
        gls[r][fq + 0] = v.x; gls[r][fq + 1] = v.y;
        gls[r][fq + 2] = v.z; gls[r][fq + 3] = v.w;
    }
    __syncthreads();

    if (tid < 32) {
        float s = 0.f;
#pragma unroll
        for (int f = 0; f < 32; f++) s = fmaf(asm_[f], grs[tid][f], s);
        prs[tid] = s;
    } else if (tid < 96) {
        int j = tid - 32;
        float s = 0.f;
#pragma unroll
        for (int f = 0; f < 32; f++) s = fmaf(asm_[f], gls[j][f], s);
        pls[j] = s;
    }

    float acc[2][4];
#pragma unroll
    for (int r = 0; r < 2; r++)
#pragma unroll
        for (int q = 0; q < 4; q++) acc[r][q] = 0.f;

#pragma unroll
    for (int f = 0; f < 32; f++) {
        float av = asm_[f];
        float gr0 = grs[ti * 2][f];
        float gr1 = grs[ti * 2 + 1][f];
        float gl[4];
#pragma unroll
        for (int q = 0; q < 4; q++) gl[q] = gls[tj + 16 * q][f];
#pragma unroll
        for (int q = 0; q < 4; q++) {
            acc[0][q] = fmaf(av, fabsf(gr0 + gl[q]), acc[0][q]);
            acc[1][q] = fmaf(av, fabsf(gr1 + gl[q]), acc[1][q]);
        }
    }
    __syncthreads();

    float* ep = es + (size_t)h * N_NODES * N_NODES;
#pragma unroll
    for (int r = 0; r < 2; r++) {
        float prv = prs[ti * 2 + r];
        float* row = ep + (size_t)(i0 + ti * 2 + r) * N_NODES + j0;
#pragma unroll
        for (int q = 0; q < 4; q++) {
            float e = fmaf(1.5f, prv + pls[tj + 16 * q], acc[r][q]);
            row[tj + 16 * q] = adjv[r][q] ? e : -1e30f;
        }
    }
}

// ---------------------------------------------------------------------------
// fused softmax + att write + res: block = IT i-rows.
#define IT 6
#define SM_SOFT (IT * NH * N_NODES * 4 + 2 * IT * GC * 4)

__global__ void __launch_bounds__(256)
softres_kernel(const float* __restrict__ es, const float* __restrict__ G,
               float* __restrict__ attO, float* __restrict__ outv, int doElu) {
    extern __shared__ float smf[];
    float* ebuf = smf;                           // [IT][NH][768]
    float* accsm = smf + IT * NH * N_NODES;      // [2][IT][GC]

    int i0 = blockIdx.x * IT;
    int tid = threadIdx.x, lane = tid & 31, w = tid >> 5;

#pragma unroll
    for (int combo = 0; combo < IT * NH; combo++) {
        int it = combo >> 2, h = combo & 3;
        if (tid < 192) {
            const float* src = es + ((size_t)h * N_NODES + i0 + it) * N_NODES;
            *(float4*)&ebuf[(it * NH + h) * N_NODES + tid * 4] =
                *(const float4*)(src + tid * 4);
        }
    }
    __syncthreads();

#pragma unroll
    for (int cc = 0; cc < 3; cc++) {
        int combo = w * 3 + cc;
        float* row = &ebuf[combo * N_NODES];
        float ev[24];
        float m = -1e30f;
#pragma unroll
        for (int k = 0; k < 24; k++) {
            ev[k] = row[lane + 32 * k];
            m = fmaxf(m, ev[k]);
        }
#pragma unroll
        for (int o = 16; o > 0; o >>= 1)
            m = fmaxf(m, __shfl_xor_sync(0xffffffffu, m, o));
        float ss = 0.f;
#pragma unroll
        for (int k = 0; k < 24; k++) {
            ev[k] = expf(ev[k] - m);
            ss += ev[k];
        }
#pragma unroll
        for (int o = 16; o > 0; o >>= 1)
            ss += __shfl_xor_sync(0xffffffffu, ss, o);
        float inv = 1.f / ss;
#pragma unroll
        for (int k = 0; k < 24; k++)
            row[lane + 32 * k] = ev[k] * inv;
    }
    __syncthreads();

    for (int idx = tid; idx < IT * N_NODES; idx += 256) {
        int it = idx / N_NODES, j = idx - it * N_NODES;
        float4 v = make_float4(ebuf[(it * NH + 0) * N_NODES + j],
                               ebuf[(it * NH + 1) * N_NODES + j],
                               ebuf[(it * NH + 2) * N_NODES + j],
                               ebuf[(it * NH + 3) * N_NODES + j]);
        *(float4*)(attO + ((size_t)(i0 + it) * N_NODES + j) * NH) = v;
    }

    int half = tid >> 7, t = tid & 127, h = t >> 5;
    float acc[IT];
#pragma unroll
    for (int it = 0; it < IT; it++) acc[it] = 0.f;

#pragma unroll 2
    for (int jj = 0; jj < 384; jj += 2) {
        int j = half * 384 + jj;
        float g0 = G[(size_t)j * GC2 + GC + t];
        float g1 = G[(size_t)(j + 1) * GC2 + GC + t];
#pragma unroll
        for (int it = 0; it < IT; it++) {
            float2 e2 = *(float2*)&ebuf[(it * NH + h) * N_NODES + j];
            acc[it] = fmaf(e2.x, g0, acc[it]);
            acc[it] = fmaf(e2.y, g1, acc[it]);
        }
    }
#pragma unroll
    for (int it = 0; it < IT; it++)
        accsm[(half * IT + it) * GC + t] = acc[it];
    __syncthreads();

    if (tid < IT * 32) {
        int it = tid >> 5, f = tid & 31;
        float m = 0.f;
#pragma unroll
        for (int hh = 0; hh < 2; hh++)
#pragma unroll
            for (int q = 0; q < 4; q++)
                m += accsm[(hh * IT + it) * GC + q * 32 + f];
        m *= 0.25f;
        if (doElu) m = (m > 0.f) ? m : expm1f(m);
        outv[(size_t)(i0 + it) * HID + f] = m;
    }
}

// ---------------------------------------------------------------------------
// fused mapper + layer-2 input GEMM: block (p, eq) computes its 24 sta rows
// then multiplies them by [Wl2|Wr2] to produce the matching G2 rows.
__global__ void mapper_gemm(const float* __restrict__ z,
                            const float* __restrict__ Wm,
                            const float* __restrict__ bm,
                            const float* __restrict__ Wl2,
                            const float* __restrict__ Wr2,
                            float* __restrict__ staO,
                            float* __restrict__ G2) {
    __shared__ float ws[SUP * 24];        // 9 KB mapper slice
    __shared__ float w2s[HID * GC2];      // 32 KB [k][n]
    __shared__ float zrow[24][HID];       // 3 KB sta rows (t-major)

    int p = blockIdx.x, eq = blockIdx.y;
    int e0 = eq * 24;
    int tid = threadIdx.x;                // 256

    for (int idx = tid; idx < SUP * 24; idx += 256) {
        int d = idx / 24, e = idx % 24;
        ws[idx] = Wm[(size_t)p * SUP * SUP + d * SUP + e0 + e];
    }
    for (int idx = tid; idx < HID * GC2; idx += 256) {
        int k = idx >> 8, n = idx & 255;
        w2s[idx] = (n < GC) ? Wl2[k * GC + n] : Wr2[k * GC + (n - GC)];
    }
    __syncthreads();

    for (int idx = tid; idx < 24 * HID; idx += 256) {
        int t = idx & 31, el = idx >> 5;
        int e = e0 + el;
        float s = bm[p * SUP + e];
#pragma unroll 4
        for (int d = 0; d < SUP; d++)
            s = fmaf(z[(size_t)(p * SUP + d) * HID + t], ws[d * 24 + el], s);
        staO[(size_t)t * N_NODES + p * SUP + e] = s;
        zrow[el][t] = s;
    }
    __syncthreads();

    // G2 rows: row i = p*96 + e0 + el, col c = tid (256 cols)
    int c = tid;
    for (int el = 0; el < 24; el++) {
        float s = 0.f;
#pragma unroll
        for (int k = 0; k < HID; k++)
            s = fmaf(zrow[el][k], w2s[k * GC2 + c], s);
        G2[(size_t)(p * SUP + e0 + el) * GC2 + c] = s;
    }
}

// ---------------------------------------------------------------------------
extern "C" void kernel_launch(void* const* d_in, const int* in_sizes, int n_in,
                              void* d_out, int out_size) {
    const float* x    = (const float*)d_in[0];
    const float* Wl1  = (const float*)d_in[1];
    const float* Wr1  = (const float*)d_in[2];
    const float* a1   = (const float*)d_in[3];
    const float* Wm   = (const float*)d_in[4];
    const float* bm   = (const float*)d_in[5];
    const float* Wl2  = (const float*)d_in[6];
    const float* Wr2  = (const float*)d_in[7];
    const float* a2   = (const float*)d_in[8];
    const int*   adjS = (const int*)d_in[9];
    const int*   adjT = (const int*)d_in[10];

    float* out  = (float*)d_out;
    float* attS = out + N_NODES * HID;
    float* attT = attS + (size_t)N_NODES * N_NODES * NH;
    float* staO = attT + (size_t)N_NODES * N_NODES * NH;

    float *gp, *g1, *g2, *z1, *es;
    __half *wi;
    int *cnt;
    cudaGetSymbolAddress((void**)&gp, d_Gp);
    cudaGetSymbolAddress((void**)&g1, d_G1);
    cudaGetSymbolAddress((void**)&g2, d_G2);
    cudaGetSymbolAddress((void**)&z1, d_z1);
    cudaGetSymbolAddress((void**)&es, d_es);
    cudaGetSymbolAddress((void**)&wi, d_Wimg);
    cudaGetSymbolAddress((void**)&cnt, d_cnt);

    const int SMEM_GEMM = 4 * A_HALF * 2 + 2 * B_BLK + 64;   // 108608
    cudaFuncSetAttribute(gemm_tc, cudaFuncAttributeMaxDynamicSharedMemorySize,
                         SMEM_GEMM);
    cudaFuncSetAttribute(softres_kernel, cudaFuncAttributeMaxDynamicSharedMemorySize,
                         SM_SOFT);

    // layer 1
    split_w<<<GSPLITS * NSTAGE, 256>>>(Wl1, Wr1, wi);
    gemm_tc<<<dim3(NMB, GSPLITS), 512, SMEM_GEMM>>>(x, wi, gp, g1, cnt);
    e_kernel<<<dim3(N_NODES / 32, N_NODES / 64, NH), 256>>>(g1, adjS, a1, es);
    softres_kernel<<<N_NODES / IT, 256, SM_SOFT>>>(es, g1, attS, z1, 1);

    // mapper + layer-2 input projection (fused)
    mapper_gemm<<<dim3(P_PATCH, 4), 256>>>(z1, Wm, bm, Wl2, Wr2, staO, g2);

    // layer 2
    e_kernel<<<dim3(N_NODES / 32, N_NODES / 64, NH), 256>>>(g2, adjT, a2, es);
    softres_kernel<<<N_NODES / IT, 256, SM_SOFT>>>(es, g2, attT, out, 0);
}

// round 16
// speedup vs baseline: 1.1273x; 1.1273x over previous
#include <cuda_runtime.h>
#include <cuda_fp16.h>
#include <math.h>
#include <stdint.h>

#define N_NODES 768
#define WAV 6360
#define HID 32
#define NH 4
#define GC 128          // H*HID
#define GC2 256         // [g_l | g_r]
#define P_PATCH 8
#define SUP 96

#define GSPLITS 24
#define CHUNK 288       // 24*288 = 6912 >= 6360 (tail zero-filled)
#define NSTAGE 9        // CHUNK / 32
#define MTILE 128
#define NMB (N_NODES / MTILE)   // 6

#define ASTR 40                 // A smem row stride (halfs)
#define A_HALF (MTILE * ASTR)   // 5120 halfs = 10240 B per half-matrix stage
#define BSTR 264                // B smem row stride (halfs) -> 528 B rows
#define B_IMG 16896             // 32 rows * 528 B (one half-matrix)
#define B_BLK 33792             // hi + lo

// device scratch (no allocation allowed)
__device__ float  d_Gp[GSPLITS * N_NODES * GC2];
__device__ float  d_G1[N_NODES * GC2];
__device__ float  d_G2[N_NODES * GC2];
__device__ float  d_z1[N_NODES * HID];
__device__ float  d_es[NH * N_NODES * N_NODES];   // e scores [h][i][j]
__device__ __half d_Wimg[GSPLITS * NSTAGE * B_BLK / 2];   // padded B stage images

// ---------------------------------------------------------------------------
__device__ __forceinline__ uint32_t smem_u32(const void* p) {
    uint32_t a;
    asm("{ .reg .u64 t; cvta.to.shared.u64 t, %1; cvt.u32.u64 %0, t; }"
        : "=r"(a) : "l"(p));
    return a;
}
__device__ __forceinline__ void ldsm_x4(uint32_t* r, uint32_t a) {
    asm volatile("ldmatrix.sync.aligned.m8n8.x4.shared.b16 {%0,%1,%2,%3}, [%4];"
                 : "=r"(r[0]), "=r"(r[1]), "=r"(r[2]), "=r"(r[3]) : "r"(a));
}
__device__ __forceinline__ void ldsm_x4t(uint32_t* r, uint32_t a) {
    asm volatile("ldmatrix.sync.aligned.m8n8.x4.trans.shared.b16 {%0,%1,%2,%3}, [%4];"
                 : "=r"(r[0]), "=r"(r[1]), "=r"(r[2]), "=r"(r[3]) : "r"(a));
}
__device__ __forceinline__ void mma_f16(float* c, const uint32_t* a, const uint32_t* b) {
    asm volatile("mma.sync.aligned.m16n8k16.row.col.f32.f16.f16.f32 "
                 "{%0,%1,%2,%3}, {%4,%5,%6,%7}, {%8,%9}, {%0,%1,%2,%3};"
                 : "+f"(c[0]), "+f"(c[1]), "+f"(c[2]), "+f"(c[3])
                 : "r"(a[0]), "r"(a[1]), "r"(a[2]), "r"(a[3]), "r"(b[0]), "r"(b[1]));
}
__device__ __forceinline__ void bulk_cp(uint32_t dst, const void* src, uint32_t bytes,
                                        uint32_t mbar) {
    asm volatile(
        "cp.async.bulk.shared::cluster.global.mbarrier::complete_tx::bytes "
        "[%0], [%1], %2, [%3];"
        :: "r"(dst), "l"(src), "r"(bytes), "r"(mbar) : "memory");
}
#define MBAR_INIT(a, n) \
    asm volatile("mbarrier.init.shared.b64 [%0], %1;" :: "r"(a), "r"(n) : "memory")
#define MBAR_INVAL(a) \
    asm volatile("mbarrier.inval.shared.b64 [%0];" :: "r"(a) : "memory")
#define MBAR_EXPECT(a, b) \
    asm volatile("mbarrier.arrive.expect_tx.shared.b64 _, [%0], %1;" \
                 :: "r"(a), "r"((uint32_t)(b)) : "memory")

__device__ __forceinline__ void mbar_wait(uint32_t mbar, uint32_t parity) {
    uint32_t done;
    asm volatile("{\n\t.reg .pred p;\n\t"
                 "mbarrier.try_wait.parity.acquire.cta.shared::cta.b64 p, [%1], %2;\n\t"
                 "selp.b32 %0, 1, 0, p;\n\t}"
                 : "=r"(done) : "r"(mbar), "r"(parity) : "memory");
    if (!done) {
        asm volatile("{\n\t.reg .pred P1;\n\t"
                     "W1_%=:\n\t"
                     "mbarrier.try_wait.parity.acquire.cta.shared::cta.b64 P1, [%0], %1, 0x989680;\n\t"
                     "@P1 bra.uni W2_%=;\n\t"
                     "bra.uni W1_%=;\n\t"
                     "W2_%=:\n\t}"
                     :: "r"(mbar), "r"(parity) : "memory");
    }
}

// ---------------------------------------------------------------------------
// split_w: [Wl|Wr] fp32 -> per-(s,st) padded smem images (hi | lo)
__global__ void split_w(const float* __restrict__ Wl, const float* __restrict__ Wr,
                        __half* __restrict__ Wi) {
    int blk = blockIdx.x;                 // s*NSTAGE + st
    int st = blk % NSTAGE, s = blk / NSTAGE;
    int tid = threadIdx.x;                // 256
    int k = tid >> 3, n0 = (tid & 7) * 32;
    int kg = s * CHUNK + st * 32 + k;

    __half hi[32], lo[32];
    if (kg < WAV) {
#pragma unroll
        for (int q = 0; q < 32; q += 2) {
            int n = n0 + q;
            float v0 = (n < GC) ? Wl[(size_t)kg * GC + n]
                                : Wr[(size_t)kg * GC + (n - GC)];
            float v1 = (n + 1 < GC) ? Wl[(size_t)kg * GC + n + 1]
                                    : Wr[(size_t)kg * GC + (n + 1 - GC)];
            __half2 h2 = __floats2half2_rn(v0, v1);
            float2 bk = __half22float2(h2);
            __half2 l2 = __floats2half2_rn(v0 - bk.x, v1 - bk.y);
            *(__half2*)(hi + q) = h2;
            *(__half2*)(lo + q) = l2;
        }
    } else {
#pragma unroll
        for (int q = 0; q < 32; q++) { hi[q] = __float2half_rn(0.f); lo[q] = hi[q]; }
    }
    char* dst = (char*)Wi + (size_t)blk * B_BLK + k * 528 + n0 * 2;
#pragma unroll
    for (int q = 0; q < 4; q++) {
        *(uint4*)(dst + q * 16)         = *(uint4*)(hi + q * 8);
        *(uint4*)(dst + B_IMG + q * 16) = *(uint4*)(lo + q * 8);
    }
}

// ---------------------------------------------------------------------------
// fp16-split tensor-core GEMM: tile 128x256, 512 thr (16 warps 4m x 4n).
// A: LDG fp32 + f16x2 cvt. B: one cp.async.bulk per stage. (R14 exact)
__global__ void __launch_bounds__(512, 1)
gemm_tc(const float* __restrict__ X,
        const __half* __restrict__ Wi,
        float* __restrict__ Gp) {
    extern __shared__ __half sm[];
    __half* Ah = sm;                      // [2][A_HALF]
    __half* Al = Ah + 2 * A_HALF;         // [2][A_HALF]
    char*   Bb = (char*)(sm + 4 * A_HALF);    // [2][B_BLK]
    uint32_t sAh = smem_u32(Ah);
    uint32_t sAl = smem_u32(Al);
    uint32_t sB  = smem_u32(Bb);
    uint32_t mbar = sB + 2 * B_BLK;

    int bm = blockIdx.x, s = blockIdx.y;
    int tid = threadIdx.x, lane = tid & 31, w = tid >> 5;
    int wm = w >> 2, wn = w & 3;
    int m0 = bm * MTILE;
    int k0 = s * CHUNK;

    if (tid == 0) { MBAR_INIT(mbar, 1); MBAR_INIT(mbar + 8, 1); }
    __syncthreads();

    const char* Bbase = (const char*)Wi + (size_t)(s * NSTAGE) * B_BLK;
    int arow = tid >> 2, aq = (tid & 3) * 4;

    auto issueB = [&](int st) {
        if (tid == 0) {
            uint32_t mb = mbar + (st & 1) * 8;
            MBAR_EXPECT(mb, B_BLK);
            bulk_cp(sB + (st & 1) * B_BLK, Bbase + (size_t)st * B_BLK, B_BLK, mb);
        }
    };

    float acc[2][8][4];
#pragma unroll
    for (int mt = 0; mt < 2; mt++)
#pragma unroll
        for (int nt = 0; nt < 8; nt++)
#pragma unroll
            for (int c = 0; c < 4; c++) acc[mt][nt][c] = 0.f;

    float4 a0, a1;

    auto ldgA = [&](int st) {
        int kt = k0 + st * 32;
        const float* p = X + (size_t)(m0 + arow) * WAV + kt;
        a0 = (kt + aq + 3 < WAV) ? *(const float4*)(p + aq)
                                 : make_float4(
            (kt + aq + 0 < WAV) ? p[aq + 0] : 0.f,
            (kt + aq + 1 < WAV) ? p[aq + 1] : 0.f,
            (kt + aq + 2 < WAV) ? p[aq + 2] : 0.f,
            (kt + aq + 3 < WAV) ? p[aq + 3] : 0.f);
        a1 = (kt + aq + 19 < WAV) ? *(const float4*)(p + aq + 16)
                                  : make_float4(
            (kt + aq + 16 < WAV) ? p[aq + 16] : 0.f,
            (kt + aq + 17 < WAV) ? p[aq + 17] : 0.f,
            (kt + aq + 18 < WAV) ? p[aq + 18] : 0.f,
            (kt + aq + 19 < WAV) ? p[aq + 19] : 0.f);
    };
    auto stsA = [&](int st) {
        int base = (st & 1) * A_HALF + arow * ASTR;
#pragma unroll
        for (int hv = 0; hv < 2; hv++) {
            float4 v = hv ? a1 : a0;
            int off = base + aq + hv * 16;
            __half2 h0 = __floats2half2_rn(v.x, v.y);
            __half2 h1 = __floats2half2_rn(v.z, v.w);
            float2 b0 = __half22float2(h0);
            float2 b1 = __half22float2(h1);
            __half2 l0 = __floats2half2_rn(v.x - b0.x, v.y - b0.y);
            __half2 l1 = __floats2half2_rn(v.z - b1.x, v.w - b1.y);
            uint2 uh, ul;
            uh.x = *(uint32_t*)&h0; uh.y = *(uint32_t*)&h1;
            ul.x = *(uint32_t*)&l0; ul.y = *(uint32_t*)&l1;
            *(uint2*)(Ah + off) = uh;
            *(uint2*)(Al + off) = ul;
        }
    };
    auto compute = [&](int b) {
        uint32_t aOffH = sAh + (uint32_t)(b * A_HALF) * 2;
        uint32_t aOffL = sAl + (uint32_t)(b * A_HALF) * 2;
        uint32_t bOffH = sB + (uint32_t)(b * B_BLK);
        uint32_t bOffL = bOffH + B_IMG;
        int l15 = lane & 15, lhi = (lane >> 4) << 3;
#pragma unroll
        for (int k16 = 0; k16 < 32; k16 += 16) {
            uint32_t ah[2][4], al[2][4];
#pragma unroll
            for (int mt = 0; mt < 2; mt++) {
                uint32_t off = (uint32_t)((wm * 32 + mt * 16 + l15) * ASTR + k16 + lhi) * 2;
                ldsm_x4(ah[mt], aOffH + off);
                ldsm_x4(al[mt], aOffL + off);
            }
#pragma unroll
            for (int p = 0; p < 4; p++) {
                uint32_t offb = (uint32_t)((k16 + l15) * BSTR + wn * 64 + p * 16 + lhi) * 2;
                uint32_t bh[4], bl[4];
                ldsm_x4t(bh, bOffH + offb);
                ldsm_x4t(bl, bOffL + offb);
#pragma unroll
                for (int mt = 0; mt < 2; mt++) {
                    mma_f16(acc[mt][2 * p],     ah[mt], bh);
                    mma_f16(acc[mt][2 * p],     ah[mt], bl);
                    mma_f16(acc[mt][2 * p],     al[mt], bh);
                    mma_f16(acc[mt][2 * p + 1], ah[mt], bh + 2);
                    mma_f16(acc[mt][2 * p + 1], ah[mt], bl + 2);
                    mma_f16(acc[mt][2 * p + 1], al[mt], bh + 2);
                }
            }
        }
    };

    // prologue
    ldgA(0); stsA(0);
    issueB(0); issueB(1);
    for (int it = 0; it < NSTAGE; it++) {
        if (it + 1 < NSTAGE) ldgA(it + 1);
        mbar_wait(mbar + (it & 1) * 8, (it >> 1) & 1);
        __syncthreads();
        compute(it & 1);
        __syncthreads();
        if (it + 1 < NSTAGE) stsA(it + 1);
        if (it + 2 < NSTAGE) issueB(it + 2);
    }

    float* out = Gp + (size_t)s * N_NODES * GC2;
    int gid = lane >> 2, tig = lane & 3;
#pragma unroll
    for (int mt = 0; mt < 2; mt++) {
        int r = m0 + wm * 32 + mt * 16 + gid;
#pragma unroll
        for (int nt = 0; nt < 8; nt++) {
            int c = wn * 64 + nt * 8 + tig * 2;
            *(float2*)&out[(size_t)r * GC2 + c] =
                make_float2(acc[mt][nt][0], acc[mt][nt][1]);
            *(float2*)&out[(size_t)(r + 8) * GC2 + c] =
                make_float2(acc[mt][nt][2], acc[mt][nt][3]);
        }
    }
    __syncthreads();
    if (tid == 0) { MBAR_INVAL(mbar); MBAR_INVAL(mbar + 8); }
}

// vectorized split reduce (standalone, full-chip — R14 form)
__global__ void reduce_split(const float* __restrict__ Gp, float* __restrict__ G) {
    int i4 = blockIdx.x * 256 + threadIdx.x;      // 49152 float4 slots
    float4 s = make_float4(0.f, 0.f, 0.f, 0.f);
#pragma unroll
    for (int p = 0; p < GSPLITS; p++) {
        float4 v = *(const float4*)(Gp + (size_t)p * (N_NODES * GC2) + i4 * 4);
        s.x += v.x; s.y += v.y; s.z += v.z; s.w += v.w;
    }
    *(float4*)(G + i4 * 4) = s;
}

// ---------------------------------------------------------------------------
// e[i,j,h] = 1.5*(pr[i,h]+pl[j,h]) + sum_f (0.4 a_f)*|gr+gl|; h = blockIdx.z
// EXACT R11/R14 form (measured best)
__global__ void e_kernel(const float* __restrict__ G,
                         const int* __restrict__ adj,
                         const float* __restrict__ avec,
                         float* __restrict__ es) {
    __shared__ float grs[32][33];
    __shared__ float gls[64][33];
    __shared__ float asm_[32];
    __shared__ float prs[32];
    __shared__ float pls[64];

    int i0 = blockIdx.x * 32, j0 = blockIdx.y * 64, h = blockIdx.z;
    int tid = threadIdx.x;
    int tj = tid & 15, ti = tid >> 4;

    if (tid < 32) asm_[tid] = 0.4f * avec[tid];

    int adjv[2][4];
#pragma unroll
    for (int r = 0; r < 2; r++)
#pragma unroll
        for (int q = 0; q < 4; q++)
            adjv[r][q] = adj[(size_t)(i0 + ti * 2 + r) * N_NODES + j0 + tj + 16 * q];

    {
        int r = tid >> 3, fq = (tid & 7) * 4;
        float4 v = *(const float4*)(G + (size_t)(i0 + r) * GC2 + GC + h * 32 + fq);
        grs[r][fq + 0] = v.x; grs[r][fq + 1] = v.y;
        grs[r][fq + 2] = v.z; grs[r][fq + 3] = v.w;
    }
#pragma unroll
    for (int e2 = 0; e2 < 2; e2++) {
        int slot = tid + e2 * 256;
        int r = slot >> 3, fq = (slot & 7) * 4;
        float4 v = *(const float4*)(G + (size_t)(j0 + r) * GC2 + h * 32 + fq);
        gls[r][fq + 0] = v.x; gls[r][fq + 1] = v.y;
        gls[r][fq + 2] = v.z; gls[r][fq + 3] = v.w;
    }
    __syncthreads();

    if (tid < 32) {
        float s = 0.f;
#pragma unroll
        for (int f = 0; f < 32; f++) s = fmaf(asm_[f], grs[tid][f], s);
        prs[tid] = s;
    } else if (tid < 96) {
        int j = tid - 32;
        float s = 0.f;
#pragma unroll
        for (int f = 0; f < 32; f++) s = fmaf(asm_[f], gls[j][f], s);
        pls[j] = s;
    }

    float acc[2][4];
#pragma unroll
    for (int r = 0; r < 2; r++)
#pragma unroll
        for (int q = 0; q < 4; q++) acc[r][q] = 0.f;

#pragma unroll
    for (int f = 0; f < 32; f++) {
        float av = asm_[f];
        float gr0 = grs[ti * 2][f];
        float gr1 = grs[ti * 2 + 1][f];
        float gl[4];
#pragma unroll
        for (int q = 0; q < 4; q++) gl[q] = gls[tj + 16 * q][f];
#pragma unroll
        for (int q = 0; q < 4; q++) {
            acc[0][q] = fmaf(av, fabsf(gr0 + gl[q]), acc[0][q]);
            acc[1][q] = fmaf(av, fabsf(gr1 + gl[q]), acc[1][q]);
        }
    }
    __syncthreads();

    float* ep = es + (size_t)h * N_NODES * N_NODES;
#pragma unroll
    for (int r = 0; r < 2; r++) {
        float prv = prs[ti * 2 + r];
        float* row = ep + (size_t)(i0 + ti * 2 + r) * N_NODES + j0;
#pragma unroll
        for (int q = 0; q < 4; q++) {
            float e = fmaf(1.5f, prv + pls[tj + 16 * q], acc[r][q]);
            row[tj + 16 * q] = adjv[r][q] ? e : -1e30f;
        }
    }
}

// ---------------------------------------------------------------------------
// fused softmax + att write + res: block = IT i-rows. (R14 exact)
#define IT 6
#define SM_SOFT (IT * NH * N_NODES * 4 + 2 * IT * GC * 4)

__global__ void __launch_bounds__(256)
softres_kernel(const float* __restrict__ es, const float* __restrict__ G,
               float* __restrict__ attO, float* __restrict__ outv, int doElu) {
    extern __shared__ float smf[];
    float* ebuf = smf;                           // [IT][NH][768]
    float* accsm = smf + IT * NH * N_NODES;      // [2][IT][GC]

    int i0 = blockIdx.x * IT;
    int tid = threadIdx.x, lane = tid & 31, w = tid >> 5;

#pragma unroll
    for (int combo = 0; combo < IT * NH; combo++) {
        int it = combo >> 2, h = combo & 3;
        if (tid < 192) {
            const float* src = es + ((size_t)h * N_NODES + i0 + it) * N_NODES;
            *(float4*)&ebuf[(it * NH + h) * N_NODES + tid * 4] =
                *(const float4*)(src + tid * 4);
        }
    }
    __syncthreads();

#pragma unroll
    for (int cc = 0; cc < 3; cc++) {
        int combo = w * 3 + cc;
        float* row = &ebuf[combo * N_NODES];
        float ev[24];
        float m = -1e30f;
#pragma unroll
        for (int k = 0; k < 24; k++) {
            ev[k] = row[lane + 32 * k];
            m = fmaxf(m, ev[k]);
        }
#pragma unroll
        for (int o = 16; o > 0; o >>= 1)
            m = fmaxf(m, __shfl_xor_sync(0xffffffffu, m, o));
        float ss = 0.f;
#pragma unroll
        for (int k = 0; k < 24; k++) {
            ev[k] = expf(ev[k] - m);
            ss += ev[k];
        }
#pragma unroll
        for (int o = 16; o > 0; o >>= 1)
            ss += __shfl_xor_sync(0xffffffffu, ss, o);
        float inv = 1.f / ss;
#pragma unroll
        for (int k = 0; k < 24; k++)
            row[lane + 32 * k] = ev[k] * inv;
    }
    __syncthreads();

    for (int idx = tid; idx < IT * N_NODES; idx += 256) {
        int it = idx / N_NODES, j = idx - it * N_NODES;
        float4 v = make_float4(ebuf[(it * NH + 0) * N_NODES + j],
                               ebuf[(it * NH + 1) * N_NODES + j],
                               ebuf[(it * NH + 2) * N_NODES + j],
                               ebuf[(it * NH + 3) * N_NODES + j]);
        *(float4*)(attO + ((size_t)(i0 + it) * N_NODES + j) * NH) = v;
    }

    int half = tid >> 7, t = tid & 127, h = t >> 5;
    float acc[IT];
#pragma unroll
    for (int it = 0; it < IT; it++) acc[it] = 0.f;

#pragma unroll 2
    for (int jj = 0; jj < 384; jj += 2) {
        int j = half * 384 + jj;
        float g0 = G[(size_t)j * GC2 + GC + t];
        float g1 = G[(size_t)(j + 1) * GC2 + GC + t];
#pragma unroll
        for (int it = 0; it < IT; it++) {
            float2 e2 = *(float2*)&ebuf[(it * NH + h) * N_NODES + j];
            acc[it] = fmaf(e2.x, g0, acc[it]);
            acc[it] = fmaf(e2.y, g1, acc[it]);
        }
    }
#pragma unroll
    for (int it = 0; it < IT; it++)
        accsm[(half * IT + it) * GC + t] = acc[it];
    __syncthreads();

    if (tid < IT * 32) {
        int it = tid >> 5, f = tid & 31;
        float m = 0.f;
#pragma unroll
        for (int hh = 0; hh < 2; hh++)
#pragma unroll
            for (int q = 0; q < 4; q++)
                m += accsm[(hh * IT + it) * GC + q * 32 + f];
        m *= 0.25f;
        if (doElu) m = (m > 0.f) ? m : expm1f(m);
        outv[(size_t)(i0 + it) * HID + f] = m;
    }
}

// ---------------------------------------------------------------------------
// fused mapper + layer-2 input GEMM (kept from R15 — isolated benign fusion)
__global__ void mapper_gemm(const float* __restrict__ z,
                            const float* __restrict__ Wm,
                            const float* __restrict__ bm,
                            const float* __restrict__ Wl2,
                            const float* __restrict__ Wr2,
                            float* __restrict__ staO,
                            float* __restrict__ G2) {
    __shared__ float ws[SUP * 24];        // 9 KB mapper slice
    __shared__ float w2s[HID * GC2];      // 32 KB [k][n]
    __shared__ float zrow[24][HID];       // 3 KB sta rows

    int p = blockIdx.x, eq = blockIdx.y;
    int e0 = eq * 24;
    int tid = threadIdx.x;                // 256

    for (int idx = tid; idx < SUP * 24; idx += 256) {
        int d = idx / 24, e = idx % 24;
        ws[idx] = Wm[(size_t)p * SUP * SUP + d * SUP + e0 + e];
    }
    for (int idx = tid; idx < HID * GC2; idx += 256) {
        int k = idx >> 8, n = idx & 255;
        w2s[idx] = (n < GC) ? Wl2[k * GC + n] : Wr2[k * GC + (n - GC)];
    }
    __syncthreads();

    for (int idx = tid; idx < 24 * HID; idx += 256) {
        int t = idx & 31, el = idx >> 5;
        int e = e0 + el;
        float s = bm[p * SUP + e];
#pragma unroll 4
        for (int d = 0; d < SUP; d++)
            s = fmaf(z[(size_t)(p * SUP + d) * HID + t], ws[d * 24 + el], s);
        staO[(size_t)t * N_NODES + p * SUP + e] = s;
        zrow[el][t] = s;
    }
    __syncthreads();

    int c = tid;
    for (int el = 0; el < 24; el++) {
        float s = 0.f;
#pragma unroll
        for (int k = 0; k < HID; k++)
            s = fmaf(zrow[el][k], w2s[k * GC2 + c], s);
        G2[(size_t)(p * SUP + e0 + el) * GC2 + c] = s;
    }
}

// ---------------------------------------------------------------------------
extern "C" void kernel_launch(void* const* d_in, const int* in_sizes, int n_in,
                              void* d_out, int out_size) {
    const float* x    = (const float*)d_in[0];
    const float* Wl1  = (const float*)d_in[1];
    const float* Wr1  = (const float*)d_in[2];
    const float* a1   = (const float*)d_in[3];
    const float* Wm   = (const float*)d_in[4];
    const float* bm   = (const float*)d_in[5];
    const float* Wl2  = (const float*)d_in[6];
    const float* Wr2  = (const float*)d_in[7];
    const float* a2   = (const float*)d_in[8];
    const int*   adjS = (const int*)d_in[9];
    const int*   adjT = (const int*)d_in[10];

    float* out  = (float*)d_out;
    float* attS = out + N_NODES * HID;
    float* attT = attS + (size_t)N_NODES * N_NODES * NH;
    float* staO = attT + (size_t)N_NODES * N_NODES * NH;

    float *gp, *g1, *g2, *z1, *es;
    __half *wi;
    cudaGetSymbolAddress((void**)&gp, d_Gp);
    cudaGetSymbolAddress((void**)&g1, d_G1);
    cudaGetSymbolAddress((void**)&g2, d_G2);
    cudaGetSymbolAddress((void**)&z1, d_z1);
    cudaGetSymbolAddress((void**)&es, d_es);
    cudaGetSymbolAddress((void**)&wi, d_Wimg);

    const int SMEM_GEMM = 4 * A_HALF * 2 + 2 * B_BLK + 64;   // 108608
    cudaFuncSetAttribute(gemm_tc, cudaFuncAttributeMaxDynamicSharedMemorySize,
                         SMEM_GEMM);
    cudaFuncSetAttribute(softres_kernel, cudaFuncAttributeMaxDynamicSharedMemorySize,
                         SM_SOFT);

    // layer 1
    split_w<<<GSPLITS * NSTAGE, 256>>>(Wl1, Wr1, wi);
    gemm_tc<<<dim3(NMB, GSPLITS), 512, SMEM_GEMM>>>(x, wi, gp);
    reduce_split<<<N_NODES * GC2 / 1024, 256>>>(gp, g1);
    e_kernel<<<dim3(N_NODES / 32, N_NODES / 64, NH), 256>>>(g1, adjS, a1, es);
    softres_kernel<<<N_NODES / IT, 256, SM_SOFT>>>(es, g1, attS, z1, 1);

    // mapper + layer-2 input projection (fused)
    mapper_gemm<<<dim3(P_PATCH, 4), 256>>>(z1, Wm, bm, Wl2, Wr2, staO, g2);

    // layer 2
    e_kernel<<<dim3(N_NODES / 32, N_NODES / 64, NH), 256>>>(g2, adjT, a2, es);
    softres_kernel<<<N_NODES / IT, 256, SM_SOFT>>>(es, g2, attT, out, 0);
}

// round 17
// speedup vs baseline: 1.1666x; 1.0348x over previous
#include <cuda_runtime.h>
#include <cuda_fp16.h>
#include <math.h>
#include <stdint.h>

#define N_NODES 768
#define WAV 6360
#define HID 32
#define NH 4
#define GC 128          // H*HID
#define GC2 256         // [g_l | g_r]
#define P_PATCH 8
#define SUP 96

#define GSPLITS 24
#define CHUNK 288       // 24*288 = 6912 >= 6360 (tail zero-filled)
#define NSTAGE 9        // CHUNK / 32
#define MTILE 128
#define NMB (N_NODES / MTILE)   // 6

#define ASTR 40                 // A smem row stride (halfs)
#define A_HALF (MTILE * ASTR)   // 5120 halfs = 10240 B per half-matrix stage
#define BSTR 264                // B smem row stride (halfs) -> 528 B rows
#define B_IMG 16896             // 32 rows * 528 B (one half-matrix)
#define B_BLK 33792             // hi + lo

// device scratch (no allocation allowed)
__device__ float  d_Gp[GSPLITS * N_NODES * GC2];
__device__ float  d_G1[N_NODES * GC2];
__device__ float  d_G2[N_NODES * GC2];
__device__ float  d_z1[N_NODES * HID];
__device__ float  d_zh[N_NODES * HID];
__device__ float  d_es[NH * N_NODES * N_NODES];   // e scores [h][i][j]
__device__ __half d_Wimg[GSPLITS * NSTAGE * B_BLK / 2];   // padded B stage images

// ---------------------------------------------------------------------------
__device__ __forceinline__ uint32_t smem_u32(const void* p) {
    uint32_t a;
    asm("{ .reg .u64 t; cvta.to.shared.u64 t, %1; cvt.u32.u64 %0, t; }"
        : "=r"(a) : "l"(p));
    return a;
}
__device__ __forceinline__ void ldsm_x4(uint32_t* r, uint32_t a) {
    asm volatile("ldmatrix.sync.aligned.m8n8.x4.shared.b16 {%0,%1,%2,%3}, [%4];"
                 : "=r"(r[0]), "=r"(r[1]), "=r"(r[2]), "=r"(r[3]) : "r"(a));
}
__device__ __forceinline__ void ldsm_x4t(uint32_t* r, uint32_t a) {
    asm volatile("ldmatrix.sync.aligned.m8n8.x4.trans.shared.b16 {%0,%1,%2,%3}, [%4];"
                 : "=r"(r[0]), "=r"(r[1]), "=r"(r[2]), "=r"(r[3]) : "r"(a));
}
__device__ __forceinline__ void mma_f16(float* c, const uint32_t* a, const uint32_t* b) {
    asm volatile("mma.sync.aligned.m16n8k16.row.col.f32.f16.f16.f32 "
                 "{%0,%1,%2,%3}, {%4,%5,%6,%7}, {%8,%9}, {%0,%1,%2,%3};"
                 : "+f"(c[0]), "+f"(c[1]), "+f"(c[2]), "+f"(c[3])
                 : "r"(a[0]), "r"(a[1]), "r"(a[2]), "r"(a[3]), "r"(b[0]), "r"(b[1]));
}
__device__ __forceinline__ void bulk_cp(uint32_t dst, const void* src, uint32_t bytes,
                                        uint32_t mbar) {
    asm volatile(
        "cp.async.bulk.shared::cluster.global.mbarrier::complete_tx::bytes "
        "[%0], [%1], %2, [%3];"
        :: "r"(dst), "l"(src), "r"(bytes), "r"(mbar) : "memory");
}
__device__ __forceinline__ void stcs4(float* p, float4 v) {
    asm volatile("st.global.cs.v4.f32 [%0], {%1,%2,%3,%4};"
                 :: "l"(p), "f"(v.x), "f"(v.y), "f"(v.z), "f"(v.w) : "memory");
}
#define MBAR_INIT(a, n) \
    asm volatile("mbarrier.init.shared.b64 [%0], %1;" :: "r"(a), "r"(n) : "memory")
#define MBAR_INVAL(a) \
    asm volatile("mbarrier.inval.shared.b64 [%0];" :: "r"(a) : "memory")
#define MBAR_EXPECT(a, b) \
    asm volatile("mbarrier.arrive.expect_tx.shared.b64 _, [%0], %1;" \
                 :: "r"(a), "r"((uint32_t)(b)) : "memory")

__device__ __forceinline__ void mbar_wait(uint32_t mbar, uint32_t parity) {
    uint32_t done;
    asm volatile("{\n\t.reg .pred p;\n\t"
                 "mbarrier.try_wait.parity.acquire.cta.shared::cta.b64 p, [%1], %2;\n\t"
                 "selp.b32 %0, 1, 0, p;\n\t}"
                 : "=r"(done) : "r"(mbar), "r"(parity) : "memory");
    if (!done) {
        asm volatile("{\n\t.reg .pred P1;\n\t"
                     "W1_%=:\n\t"
                     "mbarrier.try_wait.parity.acquire.cta.shared::cta.b64 P1, [%0], %1, 0x989680;\n\t"
                     "@P1 bra.uni W2_%=;\n\t"
                     "bra.uni W1_%=;\n\t"
                     "W2_%=:\n\t}"
                     :: "r"(mbar), "r"(parity) : "memory");
    }
}

// ---------------------------------------------------------------------------
// split_w: [Wl|Wr] fp32 -> per-(s,st) padded smem images (hi | lo)
__global__ void split_w(const float* __restrict__ Wl, const float* __restrict__ Wr,
                        __half* __restrict__ Wi) {
    int blk = blockIdx.x;                 // s*NSTAGE + st
    int st = blk % NSTAGE, s = blk / NSTAGE;
    int tid = threadIdx.x;                // 256
    int k = tid >> 3, n0 = (tid & 7) * 32;
    int kg = s * CHUNK + st * 32 + k;

    __half hi[32], lo[32];
    if (kg < WAV) {
#pragma unroll
        for (int q = 0; q < 32; q += 2) {
            int n = n0 + q;
            float v0 = (n < GC) ? Wl[(size_t)kg * GC + n]
                                : Wr[(size_t)kg * GC + (n - GC)];
            float v1 = (n + 1 < GC) ? Wl[(size_t)kg * GC + n + 1]
                                    : Wr[(size_t)kg * GC + (n + 1 - GC)];
            __half2 h2 = __floats2half2_rn(v0, v1);
            float2 bk = __half22float2(h2);
            __half2 l2 = __floats2half2_rn(v0 - bk.x, v1 - bk.y);
            *(__half2*)(hi + q) = h2;
            *(__half2*)(lo + q) = l2;
        }
    } else {
#pragma unroll
        for (int q = 0; q < 32; q++) { hi[q] = __float2half_rn(0.f); lo[q] = hi[q]; }
    }
    char* dst = (char*)Wi + (size_t)blk * B_BLK + k * 528 + n0 * 2;
#pragma unroll
    for (int q = 0; q < 4; q++) {
        *(uint4*)(dst + q * 16)         = *(uint4*)(hi + q * 8);
        *(uint4*)(dst + B_IMG + q * 16) = *(uint4*)(lo + q * 8);
    }
}

// ---------------------------------------------------------------------------
// fp16-split tensor-core GEMM: tile 128x256, 512 thr (16 warps 4m x 4n).
// A: LDG fp32 + f16x2 cvt. B: one cp.async.bulk per stage. (R14 exact)
__global__ void __launch_bounds__(512, 1)
gemm_tc(const float* __restrict__ X,
        const __half* __restrict__ Wi,
        float* __restrict__ Gp) {
    extern __shared__ __half sm[];
    __half* Ah = sm;                      // [2][A_HALF]
    __half* Al = Ah + 2 * A_HALF;         // [2][A_HALF]
    char*   Bb = (char*)(sm + 4 * A_HALF);    // [2][B_BLK]
    uint32_t sAh = smem_u32(Ah);
    uint32_t sAl = smem_u32(Al);
    uint32_t sB  = smem_u32(Bb);
    uint32_t mbar = sB + 2 * B_BLK;

    int bm = blockIdx.x, s = blockIdx.y;
    int tid = threadIdx.x, lane = tid & 31, w = tid >> 5;
    int wm = w >> 2, wn = w & 3;
    int m0 = bm * MTILE;
    int k0 = s * CHUNK;

    if (tid == 0) { MBAR_INIT(mbar, 1); MBAR_INIT(mbar + 8, 1); }
    __syncthreads();

    const char* Bbase = (const char*)Wi + (size_t)(s * NSTAGE) * B_BLK;
    int arow = tid >> 2, aq = (tid & 3) * 4;

    auto issueB = [&](int st) {
        if (tid == 0) {
            uint32_t mb = mbar + (st & 1) * 8;
            MBAR_EXPECT(mb, B_BLK);
            bulk_cp(sB + (st & 1) * B_BLK, Bbase + (size_t)st * B_BLK, B_BLK, mb);
        }
    };

    float acc[2][8][4];
#pragma unroll
    for (int mt = 0; mt < 2; mt++)
#pragma unroll
        for (int nt = 0; nt < 8; nt++)
#pragma unroll
            for (int c = 0; c < 4; c++) acc[mt][nt][c] = 0.f;

    float4 a0, a1;

    auto ldgA = [&](int st) {
        int kt = k0 + st * 32;
        const float* p = X + (size_t)(m0 + arow) * WAV + kt;
        a0 = (kt + aq + 3 < WAV) ? *(const float4*)(p + aq)
                                 : make_float4(
            (kt + aq + 0 < WAV) ? p[aq + 0] : 0.f,
            (kt + aq + 1 < WAV) ? p[aq + 1] : 0.f,
            (kt + aq + 2 < WAV) ? p[aq + 2] : 0.f,
            (kt + aq + 3 < WAV) ? p[aq + 3] : 0.f);
        a1 = (kt + aq + 19 < WAV) ? *(const float4*)(p + aq + 16)
                                  : make_float4(
            (kt + aq + 16 < WAV) ? p[aq + 16] : 0.f,
            (kt + aq + 17 < WAV) ? p[aq + 17] : 0.f,
            (kt + aq + 18 < WAV) ? p[aq + 18] : 0.f,
            (kt + aq + 19 < WAV) ? p[aq + 19] : 0.f);
    };
    auto stsA = [&](int st) {
        int base = (st & 1) * A_HALF + arow * ASTR;
#pragma unroll
        for (int hv = 0; hv < 2; hv++) {
            float4 v = hv ? a1 : a0;
            int off = base + aq + hv * 16;
            __half2 h0 = __floats2half2_rn(v.x, v.y);
            __half2 h1 = __floats2half2_rn(v.z, v.w);
            float2 b0 = __half22float2(h0);
            float2 b1 = __half22float2(h1);
            __half2 l0 = __floats2half2_rn(v.x - b0.x, v.y - b0.y);
            __half2 l1 = __floats2half2_rn(v.z - b1.x, v.w - b1.y);
            uint2 uh, ul;
            uh.x = *(uint32_t*)&h0; uh.y = *(uint32_t*)&h1;
            ul.x = *(uint32_t*)&l0; ul.y = *(uint32_t*)&l1;
            *(uint2*)(Ah + off) = uh;
            *(uint2*)(Al + off) = ul;
        }
    };
    auto compute = [&](int b) {
        uint32_t aOffH = sAh + (uint32_t)(b * A_HALF) * 2;
        uint32_t aOffL = sAl + (uint32_t)(b * A_HALF) * 2;
        uint32_t bOffH = sB + (uint32_t)(b * B_BLK);
        uint32_t bOffL = bOffH + B_IMG;
        int l15 = lane & 15, lhi = (lane >> 4) << 3;
#pragma unroll
        for (int k16 = 0; k16 < 32; k16 += 16) {
            uint32_t ah[2][4], al[2][4];
#pragma unroll
            for (int mt = 0; mt < 2; mt++) {
                uint32_t off = (uint32_t)((wm * 32 + mt * 16 + l15) * ASTR + k16 + lhi) * 2;
                ldsm_x4(ah[mt], aOffH + off);
                ldsm_x4(al[mt], aOffL + off);
            }
#pragma unroll
            for (int p = 0; p < 4; p++) {
                uint32_t offb = (uint32_t)((k16 + l15) * BSTR + wn * 64 + p * 16 + lhi) * 2;
                uint32_t bh[4], bl[4];
                ldsm_x4t(bh, bOffH + offb);
                ldsm_x4t(bl, bOffL + offb);
#pragma unroll
                for (int mt = 0; mt < 2; mt++) {
                    mma_f16(acc[mt][2 * p],     ah[mt], bh);
                    mma_f16(acc[mt][2 * p],     ah[mt], bl);
                    mma_f16(acc[mt][2 * p],     al[mt], bh);
                    mma_f16(acc[mt][2 * p + 1], ah[mt], bh + 2);
                    mma_f16(acc[mt][2 * p + 1], ah[mt], bl + 2);
                    mma_f16(acc[mt][2 * p + 1], al[mt], bh + 2);
                }
            }
        }
    };

    // prologue
    ldgA(0); stsA(0);
    issueB(0); issueB(1);
    for (int it = 0; it < NSTAGE; it++) {
        if (it + 1 < NSTAGE) ldgA(it + 1);
        mbar_wait(mbar + (it & 1) * 8, (it >> 1) & 1);
        __syncthreads();
        compute(it & 1);
        __syncthreads();
        if (it + 1 < NSTAGE) stsA(it + 1);
        if (it + 2 < NSTAGE) issueB(it + 2);
    }

    float* out = Gp + (size_t)s * N_NODES * GC2;
    int gid = lane >> 2, tig = lane & 3;
#pragma unroll
    for (int mt = 0; mt < 2; mt++) {
        int r = m0 + wm * 32 + mt * 16 + gid;
#pragma unroll
        for (int nt = 0; nt < 8; nt++) {
            int c = wn * 64 + nt * 8 + tig * 2;
            *(float2*)&out[(size_t)r * GC2 + c] =
                make_float2(acc[mt][nt][0], acc[mt][nt][1]);
            *(float2*)&out[(size_t)(r + 8) * GC2 + c] =
                make_float2(acc[mt][nt][2], acc[mt][nt][3]);
        }
    }
    __syncthreads();
    if (tid == 0) { MBAR_INVAL(mbar); MBAR_INVAL(mbar + 8); }
}

// vectorized split reduce (standalone, full-chip — R14 form)
__global__ void reduce_split(const float* __restrict__ Gp, float* __restrict__ G) {
    int i4 = blockIdx.x * 256 + threadIdx.x;      // 49152 float4 slots
    float4 s = make_float4(0.f, 0.f, 0.f, 0.f);
#pragma unroll
    for (int p = 0; p < GSPLITS; p++) {
        float4 v = *(const float4*)(Gp + (size_t)p * (N_NODES * GC2) + i4 * 4);
        s.x += v.x; s.y += v.y; s.z += v.z; s.w += v.w;
    }
    *(float4*)(G + i4 * 4) = s;
}

// ---------------------------------------------------------------------------
// e[i,j,h] = 1.5*(pr[i,h]+pl[j,h]) + sum_f (0.4 a_f)*|gr+gl|; h = blockIdx.z
// EXACT R11/R14 form (measured best)
__global__ void e_kernel(const float* __restrict__ G,
                         const int* __restrict__ adj,
                         const float* __restrict__ avec,
                         float* __restrict__ es) {
    __shared__ float grs[32][33];
    __shared__ float gls[64][33];
    __shared__ float asm_[32];
    __shared__ float prs[32];
    __shared__ float pls[64];

    int i0 = blockIdx.x * 32, j0 = blockIdx.y * 64, h = blockIdx.z;
    int tid = threadIdx.x;
    int tj = tid & 15, ti = tid >> 4;

    if (tid < 32) asm_[tid] = 0.4f * avec[tid];

    int adjv[2][4];
#pragma unroll
    for (int r = 0; r < 2; r++)
#pragma unroll
        for (int q = 0; q < 4; q++)
            adjv[r][q] = adj[(size_t)(i0 + ti * 2 + r) * N_NODES + j0 + tj + 16 * q];

    {
        int r = tid >> 3, fq = (tid & 7) * 4;
        float4 v = *(const float4*)(G + (size_t)(i0 + r) * GC2 + GC + h * 32 + fq);
        grs[r][fq + 0] = v.x; grs[r][fq + 1] = v.y;
        grs[r][fq + 2] = v.z; grs[r][fq + 3] = v.w;
    }
#pragma unroll
    for (int e2 = 0; e2 < 2; e2++) {
        int slot = tid + e2 * 256;
        int r = slot >> 3, fq = (slot & 7) * 4;
        float4 v = *(const float4*)(G + (size_t)(j0 + r) * GC2 + h * 32 + fq);
        gls[r][fq + 0] = v.x; gls[r][fq + 1] = v.y;
        gls[r][fq + 2] = v.z; gls[r][fq + 3] = v.w;
    }
    __syncthreads();

    if (tid < 32) {
        float s = 0.f;
#pragma unroll
        for (int f = 0; f < 32; f++) s = fmaf(asm_[f], grs[tid][f], s);
        prs[tid] = s;
    } else if (tid < 96) {
        int j = tid - 32;
        float s = 0.f;
#pragma unroll
        for (int f = 0; f < 32; f++) s = fmaf(asm_[f], gls[j][f], s);
        pls[j] = s;
    }

    float acc[2][4];
#pragma unroll
    for (int r = 0; r < 2; r++)
#pragma unroll
        for (int q = 0; q < 4; q++) acc[r][q] = 0.f;

#pragma unroll
    for (int f = 0; f < 32; f++) {
        float av = asm_[f];
        float gr0 = grs[ti * 2][f];
        float gr1 = grs[ti * 2 + 1][f];
        float gl[4];
#pragma unroll
        for (int q = 0; q < 4; q++) gl[q] = gls[tj + 16 * q][f];
#pragma unroll
        for (int q = 0; q < 4; q++) {
            acc[0][q] = fmaf(av, fabsf(gr0 + gl[q]), acc[0][q]);
            acc[1][q] = fmaf(av, fabsf(gr1 + gl[q]), acc[1][q]);
        }
    }
    __syncthreads();

    float* ep = es + (size_t)h * N_NODES * N_NODES;
#pragma unroll
    for (int r = 0; r < 2; r++) {
        float prv = prs[ti * 2 + r];
        float* row = ep + (size_t)(i0 + ti * 2 + r) * N_NODES + j0;
#pragma unroll
        for (int q = 0; q < 4; q++) {
            float e = fmaf(1.5f, prv + pls[tj + 16 * q], acc[r][q]);
            row[tj + 16 * q] = adjv[r][q] ? e : -1e30f;
        }
    }
}

// ---------------------------------------------------------------------------
// fused softmax + att write + res: block = IT i-rows. (R14 + streaming att stores)
#define IT 6
#define SM_SOFT (IT * NH * N_NODES * 4 + 2 * IT * GC * 4)

__global__ void __launch_bounds__(256)
softres_kernel(const float* __restrict__ es, const float* __restrict__ G,
               float* __restrict__ attO, float* __restrict__ outv, int doElu) {
    extern __shared__ float smf[];
    float* ebuf = smf;                           // [IT][NH][768]
    float* accsm = smf + IT * NH * N_NODES;      // [2][IT][GC]

    int i0 = blockIdx.x * IT;
    int tid = threadIdx.x, lane = tid & 31, w = tid >> 5;

#pragma unroll
    for (int combo = 0; combo < IT * NH; combo++) {
        int it = combo >> 2, h = combo & 3;
        if (tid < 192) {
            const float* src = es + ((size_t)h * N_NODES + i0 + it) * N_NODES;
            *(float4*)&ebuf[(it * NH + h) * N_NODES + tid * 4] =
                *(const float4*)(src + tid * 4);
        }
    }
    __syncthreads();

#pragma unroll
    for (int cc = 0; cc < 3; cc++) {
        int combo = w * 3 + cc;
        float* row = &ebuf[combo * N_NODES];
        float ev[24];
        float m = -1e30f;
#pragma unroll
        for (int k = 0; k < 24; k++) {
            ev[k] = row[lane + 32 * k];
            m = fmaxf(m, ev[k]);
        }
#pragma unroll
        for (int o = 16; o > 0; o >>= 1)
            m = fmaxf(m, __shfl_xor_sync(0xffffffffu, m, o));
        float ss = 0.f;
#pragma unroll
        for (int k = 0; k < 24; k++) {
            ev[k] = expf(ev[k] - m);
            ss += ev[k];
        }
#pragma unroll
        for (int o = 16; o > 0; o >>= 1)
            ss += __shfl_xor_sync(0xffffffffu, ss, o);
        float inv = 1.f / ss;
#pragma unroll
        for (int k = 0; k < 24; k++)
            row[lane + 32 * k] = ev[k] * inv;
    }
    __syncthreads();

    // att gmem write with streaming hint (write-only data; keep L2 for es/G)
    for (int idx = tid; idx < IT * N_NODES; idx += 256) {
        int it = idx / N_NODES, j = idx - it * N_NODES;
        float4 v = make_float4(ebuf[(it * NH + 0) * N_NODES + j],
                               ebuf[(it * NH + 1) * N_NODES + j],
                               ebuf[(it * NH + 2) * N_NODES + j],
                               ebuf[(it * NH + 3) * N_NODES + j]);
        stcs4(attO + ((size_t)(i0 + it) * N_NODES + j) * NH, v);
    }

    int half = tid >> 7, t = tid & 127, h = t >> 5;
    float acc[IT];
#pragma unroll
    for (int it = 0; it < IT; it++) acc[it] = 0.f;

#pragma unroll 2
    for (int jj = 0; jj < 384; jj += 2) {
        int j = half * 384 + jj;
        float g0 = G[(size_t)j * GC2 + GC + t];
        float g1 = G[(size_t)(j + 1) * GC2 + GC + t];
#pragma unroll
        for (int it = 0; it < IT; it++) {
            float2 e2 = *(float2*)&ebuf[(it * NH + h) * N_NODES + j];
            acc[it] = fmaf(e2.x, g0, acc[it]);
            acc[it] = fmaf(e2.y, g1, acc[it]);
        }
    }
#pragma unroll
    for (int it = 0; it < IT; it++)
        accsm[(half * IT + it) * GC + t] = acc[it];
    __syncthreads();

    if (tid < IT * 32) {
        int it = tid >> 5, f = tid & 31;
        float m = 0.f;
#pragma unroll
        for (int hh = 0; hh < 2; hh++)
#pragma unroll
            for (int q = 0; q < 4; q++)
                m += accsm[(hh * IT + it) * GC + q * 32 + f];
        m *= 0.25f;
        if (doElu) m = (m > 0.f) ? m : expm1f(m);
        outv[(size_t)(i0 + it) * HID + f] = m;
    }
}

// ---------------------------------------------------------------------------
// mapper split 4-way over e: grid (P_PATCH, 4)  (R14 exact)
__global__ void mapper_kernel(const float* __restrict__ z,
                              const float* __restrict__ Wm,
                              const float* __restrict__ bm,
                              float* __restrict__ staO,
                              float* __restrict__ zh) {
    __shared__ float ws[SUP * 24];        // 9 KB slice
    int p = blockIdx.x, eq = blockIdx.y;
    int e0 = eq * 24;
    int tid = threadIdx.x;                // 256
    for (int idx = tid; idx < SUP * 24; idx += 256) {
        int d = idx / 24, e = idx % 24;
        ws[idx] = Wm[(size_t)p * SUP * SUP + d * SUP + e0 + e];
    }
    __syncthreads();

    for (int idx = tid; idx < 24 * HID; idx += 256) {
        int t = idx & 31, el = idx >> 5;
        int e = e0 + el;
        float s = bm[p * SUP + e];
#pragma unroll 4
        for (int d = 0; d < SUP; d++)
            s = fmaf(z[(size_t)(p * SUP + d) * HID + t], ws[d * 24 + el], s);
        staO[(size_t)t * N_NODES + p * SUP + e] = s;
        zh[(size_t)(p * SUP + e) * HID + t] = s;
    }
}

__global__ void gemm_small(const float* __restrict__ zh,
                           const float* __restrict__ Wl,
                           const float* __restrict__ Wr,
                           float* __restrict__ G) {
    __shared__ float zr[HID];
    int i = blockIdx.x;
    int c = threadIdx.x;
    if (c < HID) zr[c] = zh[(size_t)i * HID + c];
    __syncthreads();
    const float* W = (c < GC) ? Wl : Wr;
    int cc = c & 127;
    float s = 0.f;
#pragma unroll
    for (int k = 0; k < HID; k++) s = fmaf(zr[k], W[k * GC + cc], s);
    G[(size_t)i * GC2 + c] = s;
}

// ---------------------------------------------------------------------------
extern "C" void kernel_launch(void* const* d_in, const int* in_sizes, int n_in,
                              void* d_out, int out_size) {
    const float* x    = (const float*)d_in[0];
    const float* Wl1  = (const float*)d_in[1];
    const float* Wr1  = (const float*)d_in[2];
    const float* a1   = (const float*)d_in[3];
    const float* Wm   = (const float*)d_in[4];
    const float* bm   = (const float*)d_in[5];
    const float* Wl2  = (const float*)d_in[6];
    const float* Wr2  = (const float*)d_in[7];
    const float* a2   = (const float*)d_in[8];
    const int*   adjS = (const int*)d_in[9];
    const int*   adjT = (const int*)d_in[10];

    float* out  = (float*)d_out;
    float* attS = out + N_NODES * HID;
    float* attT = attS + (size_t)N_NODES * N_NODES * NH;
    float* staO = attT + (size_t)N_NODES * N_NODES * NH;

    float *gp, *g1, *g2, *z1, *zh, *es;
    __half *wi;
    cudaGetSymbolAddress((void**)&gp, d_Gp);
    cudaGetSymbolAddress((void**)&g1, d_G1);
    cudaGetSymbolAddress((void**)&g2, d_G2);
    cudaGetSymbolAddress((void**)&z1, d_z1);
    cudaGetSymbolAddress((void**)&zh, d_zh);
    cudaGetSymbolAddress((void**)&es, d_es);
    cudaGetSymbolAddress((void**)&wi, d_Wimg);

    const int SMEM_GEMM = 4 * A_HALF * 2 + 2 * B_BLK + 64;   // 108608
    cudaFuncSetAttribute(gemm_tc, cudaFuncAttributeMaxDynamicSharedMemorySize,
                         SMEM_GEMM);
    cudaFuncSetAttribute(softres_kernel, cudaFuncAttributeMaxDynamicSharedMemorySize,
                         SM_SOFT);

    // layer 1
    split_w<<<GSPLITS * NSTAGE, 256>>>(Wl1, Wr1, wi);
    gemm_tc<<<dim3(NMB, GSPLITS), 512, SMEM_GEMM>>>(x, wi, gp);
    reduce_split<<<N_NODES * GC2 / 1024, 256>>>(gp, g1);
    e_kernel<<<dim3(N_NODES / 32, N_NODES / 64, NH), 256>>>(g1, adjS, a1, es);
    softres_kernel<<<N_NODES / IT, 256, SM_SOFT>>>(es, g1, attS, z1, 1);

    // mapper
    mapper_kernel<<<dim3(P_PATCH, 4), 256>>>(z1, Wm, bm, staO, zh);

    // layer 2
    gemm_small<<<N_NODES, 256>>>(zh, Wl2, Wr2, g2);
    e_kernel<<<dim3(N_NODES / 32, N_NODES / 64, NH), 256>>>(g2, adjT, a2, es);
    softres_kernel<<<N_NODES / IT, 256, SM_SOFT>>>(es, g2, attT, out, 0);
}